// round 16
// baseline (speedup 1.0000x reference)
#include <cuda_runtime.h>
#include <cuda_fp16.h>
#include <cstdint>
#include <cstddef>

// NB=4, H=8, B=2, S=1024, D=HID=512.
// P = sum_h gate[n,h] * softmax(s[n,h] * scores);  HS = P @ V
// out = MOD * ( concat_n(HS_n) @ concat_n(Wo_n) + sum_n bo_n ).
#define MODV 1.55f
#define SCALEV 0.044194173824159216f   // 1/sqrt(512)

// ---- scratch (device globals; no allocation allowed) ----
__device__ __half g_Xh [2048u*512u];
__device__ __half g_Wh [4u*4u*512u*512u];  // [w][n][512][512], w: qT,kT,vT,oT
__device__ __half g_Qh [4u*2048u*512u];
__device__ __half g_Kh [4u*2048u*512u];
__device__ __half g_Vh [4u*2048u*512u];
__device__ __half g_VTh[8u*512u*1024u];    // per (n,b): V^T
__device__ float  g_S  [8u*1024u*1024u];   // scores (fp32)
__device__ __half g_Ph [8u*1024u*1024u];   // combined probs (fp16)
__device__ __half g_HSh[4u*2048u*512u];
__device__ float  g_OP [4u*2048u*512u];    // out split-K partials

#define MMA_F16(c, a0, a1, a2, a3, b0, b1)                                    \
    asm volatile("mma.sync.aligned.m16n8k16.row.col.f32.f16.f16.f32 "         \
        "{%0,%1,%2,%3}, {%4,%5,%6,%7}, {%8,%9}, {%0,%1,%2,%3};"               \
        : "+f"((c)[0]), "+f"((c)[1]), "+f"((c)[2]), "+f"((c)[3])              \
        : "r"(a0), "r"(a1), "r"(a2), "r"(a3), "r"(b0), "r"(b1))

#define LDSM_X4(r0, r1, r2, r3, addr)                                         \
    asm volatile("ldmatrix.sync.aligned.m8n8.x4.shared.b16 {%0,%1,%2,%3}, [%4];" \
        : "=r"(r0), "=r"(r1), "=r"(r2), "=r"(r3) : "r"(addr))
#define LDSM_X2(r0, r1, addr)                                                 \
    asm volatile("ldmatrix.sync.aligned.m8n8.x2.shared.b16 {%0,%1}, [%2];"    \
        : "=r"(r0), "=r"(r1) : "r"(addr))

#define CP_ASYNC16(dst, src)                                                   \
    asm volatile("cp.async.cg.shared.global [%0], [%1], 16;"                   \
        :: "r"(dst), "l"(src))
#define CP_COMMIT() asm volatile("cp.async.commit_group;" ::: "memory")
template<int N> __device__ __forceinline__ void cp_wait() {
    asm volatile("cp.async.wait_group %0;" :: "n"(N) : "memory");
}

// SMEM: per stage, A tile 128x32 fp16 (8KB) + B tile 128x32 fp16 (8KB).
// Row = 64B (4 x 16B chunks); chunk stored at slot (chunk ^ ((row>>1)&3)).
#define STAGEB 16384u
#define NSTAGE 4
#define GEMM_SMEM_BYTES (NSTAGE * STAGEB)   // 65536 B -> 2 CTAs/SM

// ============================================================
// fp16 tensor-core GEMM, cp.async 4-stage: C = epi(A @ B^T)
//   A: [M,K] K-major fp16: elem[m][k] = A + z*zA + (k/512)*slabA + (k%512) + m*lda
//   B: [N,K] K-major fp16, same slab scheme.
// CTA 128x128, BK=32, 256 threads; 8 warps (2 M x 4 N), each 64x32.
// 2 CTAs/SM -> 16 warps/SM for HMMA issue-slot saturation.
// EPI: 0 -> alpha*acc ; 1 -> acc + bias[z][n].  HALF_OUT: store fp16.
// ============================================================
template<int EPI, bool HALF_OUT>
__global__ void __launch_bounds__(256, 2) gemm_h(
    const __half* __restrict__ A, size_t zA, size_t slabA, int lda,
    const __half* __restrict__ B, size_t zB, size_t slabB, int ldb,
    const float* __restrict__ bias, size_t zBias,
    void* __restrict__ Cv, size_t zC, int ldc,
    int Ktot, float alpha)
{
    extern __shared__ char smc[];
    const uint32_t sbu = (uint32_t)__cvta_generic_to_shared(smc);

    const int tid  = threadIdx.x;
    const int wid  = tid >> 5;
    const int lane = tid & 31;
    const int g    = lane >> 2;
    const int tig  = lane & 3;
    const int wm   = wid & 1;      // 2 M-slabs of 64
    const int wn   = wid >> 1;     // 4 N-slabs of 32

    const __half* Az = A + (size_t)blockIdx.z * zA;
    const __half* Bz = B + (size_t)blockIdx.z * zB;
    const int m0 = blockIdx.y * 128;
    const int n0 = blockIdx.x * 128;
    const int NIT = Ktot >> 5;

    // ldmatrix per-lane address components
    const int rowA  = wm * 64 + (lane & 7) + ((lane >> 3) & 1) * 8;  // + mf*16
    const int chA   = (lane >> 4) & 1;                               // + ks*2
    const int swzA  = (rowA >> 1) & 3;     // mf*16 -> invariant
    const uint32_t aoff = (uint32_t)rowA * 64u;
    const int rowB  = wn * 32 + (lane & 7);                          // + nf*8
    const int chB   = (lane >> 3) & 1;                               // lanes 0-15
    const int swzB  = (rowB >> 1) & 3;     // nf*8 -> invariant
    const uint32_t boff = (uint32_t)rowB * 64u;

    // cp.async: per tile 512 16B-chunks; thread covers 2 (A) + 2 (B)
    auto issue = [&](int s, int itk) {
        const int k0 = itk << 5;
        const __half* Ait = Az + (size_t)(k0 >> 9) * slabA + (k0 & 511);
        const __half* Bit = Bz + (size_t)(k0 >> 9) * slabB + (k0 & 511);
        const uint32_t abase = sbu + (uint32_t)s * STAGEB;
        const uint32_t bbase = abase + 8192u;
#pragma unroll
        for (int j = 0; j < 2; j++) {
            const int f = tid + 256 * j;
            const int r = f >> 2, c = f & 3;
            const uint32_t off = (uint32_t)(r * 64) +
                                 ((uint32_t)(c ^ ((r >> 1) & 3)) << 4);
            CP_ASYNC16(abase + off, Ait + (size_t)(m0 + r) * lda + c * 8);
            CP_ASYNC16(bbase + off, Bit + (size_t)(n0 + r) * ldb + c * 8);
        }
    };

    float acc[16][4];
#pragma unroll
    for (int i = 0; i < 16; i++)
#pragma unroll
        for (int j = 0; j < 4; j++) acc[i][j] = 0.f;

    issue(0, 0); CP_COMMIT();
    issue(1, 1); CP_COMMIT();
    issue(2, 2); CP_COMMIT();

    int sc = 0, sp = 3;
    for (int it = 0; it < NIT; it++) {
        if (it < NIT - 2) cp_wait<2>();
        else if (it == NIT - 2) cp_wait<1>();
        else cp_wait<0>();
        __syncthreads();
        // stage sp == (it-1)%4: fully read at iter it-1, proven by barrier above
        if (it + 3 < NIT) { issue(sp, it + 3); CP_COMMIT(); }

        const uint32_t As = sbu + (uint32_t)sc * STAGEB;
        const uint32_t Bs = As + 8192u;
#pragma unroll
        for (int ks = 0; ks < 2; ks++) {
            uint32_t bfr[4][2];
            const uint32_t cB = ((uint32_t)((ks * 2 + chB) ^ swzB)) << 4;
#pragma unroll
            for (int nf = 0; nf < 4; nf++)
                LDSM_X2(bfr[nf][0], bfr[nf][1], Bs + boff + (uint32_t)nf * 512u + cB);
            const uint32_t cA = ((uint32_t)((ks * 2 + chA) ^ swzA)) << 4;
#pragma unroll
            for (int mf = 0; mf < 4; mf++) {
                uint32_t a0, a1, a2, a3;
                LDSM_X4(a0, a1, a2, a3, As + aoff + (uint32_t)mf * 1024u + cA);
#pragma unroll
                for (int nf = 0; nf < 4; nf++)
                    MMA_F16(acc[mf * 4 + nf], a0, a1, a2, a3, bfr[nf][0], bfr[nf][1]);
            }
        }
        sc = (sc + 1) & 3;
        sp = (sp + 1) & 3;
    }

    // ---- epilogue ----
    const float* biasz = (EPI == 1) ? (bias + (size_t)blockIdx.z * zBias) : bias;
#pragma unroll
    for (int mf = 0; mf < 4; mf++) {
        const int r0 = m0 + wm * 64 + mf * 16 + g;
#pragma unroll
        for (int nf = 0; nf < 4; nf++) {
            const int col = n0 + wn * 32 + nf * 8 + 2 * tig;
            float* c = acc[mf * 4 + nf];
            float o0, o1, o2, o3;
            if (EPI == 0) {
                o0 = c[0] * alpha; o1 = c[1] * alpha;
                o2 = c[2] * alpha; o3 = c[3] * alpha;
            } else {
                const float b0v = biasz[col], b1v = biasz[col + 1];
                o0 = c[0] + b0v; o1 = c[1] + b1v;
                o2 = c[2] + b0v; o3 = c[3] + b1v;
            }
            if (HALF_OUT) {
                __half* Ch = (__half*)Cv + (size_t)blockIdx.z * zC;
                *(__half2*)(Ch + (size_t)r0 * ldc + col) =
                    make_half2(__float2half_rn(o0), __float2half_rn(o1));
                *(__half2*)(Ch + (size_t)(r0 + 8) * ldc + col) =
                    make_half2(__float2half_rn(o2), __float2half_rn(o3));
            } else {
                float* Cf = (float*)Cv + (size_t)blockIdx.z * zC;
                *(float2*)(Cf + (size_t)r0 * ldc + col)       = make_float2(o0, o1);
                *(float2*)(Cf + (size_t)(r0 + 8) * ldc + col) = make_float2(o2, o3);
            }
        }
    }
}

// ============================================================
// convert x fp32 -> fp16
// ============================================================
__global__ void __launch_bounds__(256) convert_x_kernel(
    const float* __restrict__ in, __half* __restrict__ out)
{
    const int i = blockIdx.x * 256 + threadIdx.x;
    float4 v = ((const float4*)in)[i];
    __half2* o = (__half2*)(out + (size_t)i * 4);
    o[0] = make_half2(__float2half_rn(v.x), __float2half_rn(v.y));
    o[1] = make_half2(__float2half_rn(v.z), __float2half_rn(v.w));
}

// ============================================================
// fused 4-weight transpose fp32 -> fp16: g_Wh[w][n] = W^T
// ============================================================
__global__ void __launch_bounds__(256) transpose_w_kernel(
    const float* __restrict__ Wq, const float* __restrict__ Wk,
    const float* __restrict__ Wv, const float* __restrict__ Wo)
{
    __shared__ float t[32][33];
    const int z = blockIdx.z;
    const int w = z >> 2, n = z & 3;
    const float* src = (w == 0) ? Wq : (w == 1) ? Wk : (w == 2) ? Wv : Wo;
    src += (size_t)n * 262144u;
    __half* dst = g_Wh + (size_t)w * 1048576u + (size_t)n * 262144u;
    const int c0 = blockIdx.x * 32, r0 = blockIdx.y * 32;
    const int x = threadIdx.x, y = threadIdx.y;
#pragma unroll
    for (int j = 0; j < 32; j += 8)
        t[y + j][x] = src[(size_t)(r0 + y + j) * 512u + c0 + x];
    __syncthreads();
#pragma unroll
    for (int j = 0; j < 32; j += 8)
        dst[(size_t)(c0 + y + j) * 512u + r0 + x] = __float2half_rn(t[x][y + j]);
}

// ============================================================
// V (fp16) -> VT (fp16) per (n,b): [1024][512] -> [512][1024]
// ============================================================
__global__ void __launch_bounds__(256) transpose_vh_kernel()
{
    __shared__ __half t[32][33];
    const size_t zoff = (size_t)blockIdx.z * 524288u;
    const __half* in = g_Vh + zoff;
    __half* out = g_VTh + zoff;
    const int c0 = blockIdx.x * 32, r0 = blockIdx.y * 32;
    const int x = threadIdx.x, y = threadIdx.y;
#pragma unroll
    for (int j = 0; j < 32; j += 8)
        t[y + j][x] = in[(size_t)(r0 + y + j) * 512u + c0 + x];
    __syncthreads();
#pragma unroll
    for (int j = 0; j < 32; j += 8)
        out[(size_t)(c0 + y + j) * 1024u + r0 + x] = t[x][y + j];
}

// ============================================================
// Softmax-combine: reads fp32 g_S, writes fp16 g_Ph
// ============================================================
__global__ void __launch_bounds__(128) softmax_combine_kernel(
    const float* __restrict__ strength, const float* __restrict__ gate)
{
    __shared__ float sm[4];
    const int r   = blockIdx.x;
    const int n   = r >> 11;
    const float* row = g_S + (size_t)r * 1024u;
    __half* orow = g_Ph + (size_t)r * 1024u;
    const int tid = threadIdx.x;

    float xv[8];
#pragma unroll
    for (int j = 0; j < 8; j++) xv[j] = row[tid + 128 * j];

    float m = xv[0];
#pragma unroll
    for (int j = 1; j < 8; j++) m = fmaxf(m, xv[j]);
#pragma unroll
    for (int o = 16; o; o >>= 1) m = fmaxf(m, __shfl_xor_sync(0xffffffffu, m, o));
    if ((tid & 31) == 0) sm[tid >> 5] = m;
    __syncthreads();
    m = fmaxf(fmaxf(sm[0], sm[1]), fmaxf(sm[2], sm[3]));

    float comb[8] = {0,0,0,0,0,0,0,0};
#pragma unroll 1
    for (int h = 0; h < 8; h++) {
        const float gg = gate[n * 8 + h];
        if (gg != 0.0f) {
            float s = strength[n * 64 + h * 9];
            s = fminf(fmaxf(s, 0.01f), 1.0f);
            float e[8];
            float part = 0.f;
#pragma unroll
            for (int j = 0; j < 8; j++) { e[j] = __expf(s * (xv[j] - m)); part += e[j]; }
#pragma unroll
            for (int o = 16; o; o >>= 1) part += __shfl_xor_sync(0xffffffffu, part, o);
            __syncthreads();
            if ((tid & 31) == 0) sm[tid >> 5] = part;
            __syncthreads();
            const float inv = gg / (sm[0] + sm[1] + sm[2] + sm[3]);
#pragma unroll
            for (int j = 0; j < 8; j++) comb[j] = fmaf(e[j], inv, comb[j]);
        }
    }
#pragma unroll
    for (int j = 0; j < 8; j++) orow[tid + 128 * j] = __float2half_rn(comb[j]);
}

// ============================================================
// combine split-K partials: out = MOD*(p0+p1+p2+p3 + sum_n bo[n])
// ============================================================
__global__ void __launch_bounds__(256) combine_out_kernel(
    const float* __restrict__ bo, float* __restrict__ out)
{
    const int i = blockIdx.x * 256 + threadIdx.x;
    const int col = (i & 127) * 4;
    float4 p0 = ((const float4*)g_OP)[i];
    float4 p1 = ((const float4*)(g_OP + 1048576u))[i];
    float4 p2 = ((const float4*)(g_OP + 2097152u))[i];
    float4 p3 = ((const float4*)(g_OP + 3145728u))[i];
    float4 v;
#pragma unroll
    for (int q = 0; q < 4; q++) {
        const float bsum = bo[col + q] + bo[512 + col + q] +
                           bo[1024 + col + q] + bo[1536 + col + q];
        ((float*)&v)[q] = MODV * (((float*)&p0)[q] + ((float*)&p1)[q] +
                                  ((float*)&p2)[q] + ((float*)&p3)[q] + bsum);
    }
    ((float4*)out)[i] = v;
}

// ============================================================
extern "C" void kernel_launch(void* const* d_in, const int* in_sizes, int n_in,
                              void* d_out, int out_size)
{
    __half *Xh, *Wh, *Qh, *Kh, *Vh, *VTh, *Ph, *HSh;
    float *S, *OP;
    cudaGetSymbolAddress((void**)&Xh,  g_Xh);
    cudaGetSymbolAddress((void**)&Wh,  g_Wh);
    cudaGetSymbolAddress((void**)&Qh,  g_Qh);
    cudaGetSymbolAddress((void**)&Kh,  g_Kh);
    cudaGetSymbolAddress((void**)&Vh,  g_Vh);
    cudaGetSymbolAddress((void**)&VTh, g_VTh);
    cudaGetSymbolAddress((void**)&S,   g_S);
    cudaGetSymbolAddress((void**)&Ph,  g_Ph);
    cudaGetSymbolAddress((void**)&HSh, g_HSh);
    cudaGetSymbolAddress((void**)&OP,  g_OP);

    const float* x        = (const float*)d_in[0];
    const float* Wq       = (const float*)d_in[1];
    const float* bq       = (const float*)d_in[2];
    const float* Wk       = (const float*)d_in[3];
    const float* bk       = (const float*)d_in[4];
    const float* Wv       = (const float*)d_in[5];
    const float* bv       = (const float*)d_in[6];
    const float* Wo       = (const float*)d_in[7];
    const float* bo       = (const float*)d_in[8];
    const float* strength = (const float*)d_in[9];
    const float* gate     = (const float*)d_in[10];
    float* out = (float*)d_out;

    cudaFuncSetAttribute(gemm_h<0,false>, cudaFuncAttributeMaxDynamicSharedMemorySize, GEMM_SMEM_BYTES);
    cudaFuncSetAttribute(gemm_h<0,true>,  cudaFuncAttributeMaxDynamicSharedMemorySize, GEMM_SMEM_BYTES);
    cudaFuncSetAttribute(gemm_h<1,true>,  cudaFuncAttributeMaxDynamicSharedMemorySize, GEMM_SMEM_BYTES);

    __half* WqT = Wh;
    __half* WkT = Wh + 1048576u;
    __half* WvT = Wh + 2097152u;
    __half* WoT = Wh + 3145728u;

    const dim3 tb(32, 8);
    convert_x_kernel<<<1024, 256>>>(x, Xh);
    transpose_w_kernel<<<dim3(16, 16, 16), tb>>>(Wq, Wk, Wv, Wo);

    // 1) QKV: C[2048,512] = X @ W^T(n) + bias(n), z = n, fp16 out
    gemm_h<1,true><<<dim3(4, 16, 4), 256, GEMM_SMEM_BYTES>>>(
        Xh, 0, 512, 512,   WqT, 262144u, 512, 512,  bq, 512u,  Qh, 1048576u, 512, 512, 1.0f);
    gemm_h<1,true><<<dim3(4, 16, 4), 256, GEMM_SMEM_BYTES>>>(
        Xh, 0, 512, 512,   WkT, 262144u, 512, 512,  bk, 512u,  Kh, 1048576u, 512, 512, 1.0f);
    gemm_h<1,true><<<dim3(4, 16, 4), 256, GEMM_SMEM_BYTES>>>(
        Xh, 0, 512, 512,   WvT, 262144u, 512, 512,  bv, 512u,  Vh, 1048576u, 512, 512, 1.0f);

    // 2) scores = Q @ K^T / sqrt(512), z = (n,b), fp32 out
    gemm_h<0,false><<<dim3(8, 8, 8), 256, GEMM_SMEM_BYTES>>>(
        Qh, 524288u, 512, 512,   Kh, 524288u, 512, 512,  nullptr, 0,
        S, 1048576u, 1024, 512, SCALEV);

    // 3) gated multi-temperature softmax combine: fp32 S -> fp16 P
    softmax_combine_kernel<<<8192, 128>>>(strength, gate);

    // 3b) V^T per (n,b)
    transpose_vh_kernel<<<dim3(16, 32, 8), tb>>>();

    // 4) HS = P @ VT^T, z = (n,b): M=1024, N=512, K=1024, fp16 out
    gemm_h<0,true><<<dim3(4, 8, 8), 256, GEMM_SMEM_BYTES>>>(
        Ph, 1048576u, 512, 1024,   VTh, 524288u, 512, 1024,  nullptr, 0,
        HSh, 524288u, 512, 1024, 1.0f);

    // 5) split-K=4 out partials: z = split s, fp32 out
    gemm_h<0,false><<<dim3(4, 16, 4), 256, GEMM_SMEM_BYTES>>>(
        HSh, 1048576u, 0, 512,   WoT, 262144u, 0, 512,  nullptr, 0,
        OP, 1048576u, 512, 512, 1.0f);

    // 6) out = MOD*(sum partials + sum_n bo)
    combine_out_kernel<<<1024, 256>>>(bo, out);
}

// round 17
// speedup vs baseline: 1.1445x; 1.1445x over previous
#include <cuda_runtime.h>
#include <cuda_fp16.h>
#include <cstdint>
#include <cstddef>

// NB=4, H=8, B=2, S=1024, D=HID=512.
// P = sum_h gate[n,h] * softmax(s[n,h] * scores);  HS = P @ V
// out = MOD * ( concat_n(HS_n) @ concat_n(Wo_n) + sum_n bo_n ).
#define MODV 1.55f
#define SCALEV 0.044194173824159216f   // 1/sqrt(512)

// ---- scratch (device globals; no allocation allowed) ----
__device__ __half g_Xh  [2048u*512u];
__device__ __half g_Wh  [4u*4u*512u*512u];  // [w][n][512][512], w: qT,kT,vT,oT
__device__ float  g_QKVb[3u*4u*512u];       // concat bq,bk,bv
__device__ __half g_QKVh[12u*2048u*512u];   // [w][n][2048][512]: Q,K,V
__device__ __half g_VTh [8u*512u*1024u];    // per (n,b): V^T
__device__ float  g_S   [8u*1024u*1024u];   // scores (fp32)
__device__ __half g_Ph  [8u*1024u*1024u];   // combined probs (fp16)
__device__ __half g_HSh [4u*2048u*512u];
__device__ float  g_OP  [4u*2048u*512u];    // out split-K partials

#define MMA_F16(c, a0, a1, a2, a3, b0, b1)                                    \
    asm volatile("mma.sync.aligned.m16n8k16.row.col.f32.f16.f16.f32 "         \
        "{%0,%1,%2,%3}, {%4,%5,%6,%7}, {%8,%9}, {%0,%1,%2,%3};"               \
        : "+f"((c)[0]), "+f"((c)[1]), "+f"((c)[2]), "+f"((c)[3])              \
        : "r"(a0), "r"(a1), "r"(a2), "r"(a3), "r"(b0), "r"(b1))

#define LDSM_X4(r0, r1, r2, r3, addr)                                         \
    asm volatile("ldmatrix.sync.aligned.m8n8.x4.shared.b16 {%0,%1,%2,%3}, [%4];" \
        : "=r"(r0), "=r"(r1), "=r"(r2), "=r"(r3) : "r"(addr))

#define CP_ASYNC16(dst, src)                                                   \
    asm volatile("cp.async.cg.shared.global [%0], [%1], 16;"                   \
        :: "r"(dst), "l"(src))
#define CP_COMMIT() asm volatile("cp.async.commit_group;" ::: "memory")
template<int N> __device__ __forceinline__ void cp_wait() {
    asm volatile("cp.async.wait_group %0;" :: "n"(N) : "memory");
}

// SMEM: per stage, A tile 128x32 fp16 (8KB) + B tile 128x32 fp16 (8KB).
// Row = 64B (4 x 16B chunks); chunk stored at slot (chunk ^ ((row>>1)&3)).
#define STAGEB 16384u
#define NSTAGE 4
#define GEMM_SMEM_BYTES (NSTAGE * STAGEB)   // 65536 B -> 2 CTAs/SM

// ============================================================
// fp16 tensor-core GEMM, cp.async 4-stage: C = epi(A @ B^T)
//   A: [M,K] K-major fp16: elem[m][k] = A + z*zA + (k/512)*slabA + (k%512) + m*lda
//   B: [N,K] K-major fp16, same slab scheme.
// CTA 128x128, BK=32, 128 threads; 4 warps (2 M x 2 N), each 64x64.
// (R14 config: best measured; mma.sync issue-path is the ceiling.)
// B fragments via paired ldmatrix.x4 (2 nf per instr) to cut LDSM count.
// EPI: 0 -> alpha*acc ; 1 -> acc + bias[z][n].  HALF_OUT: store fp16.
// ============================================================
template<int EPI, bool HALF_OUT>
__global__ void __launch_bounds__(128, 2) gemm_h(
    const __half* __restrict__ A, size_t zA, size_t slabA, int lda,
    const __half* __restrict__ B, size_t zB, size_t slabB, int ldb,
    const float* __restrict__ bias, size_t zBias,
    void* __restrict__ Cv, size_t zC, int ldc,
    int Ktot, float alpha)
{
    extern __shared__ char smc[];
    const uint32_t sbu = (uint32_t)__cvta_generic_to_shared(smc);

    const int tid  = threadIdx.x;
    const int wid  = tid >> 5;
    const int lane = tid & 31;
    const int g    = lane >> 2;
    const int tig  = lane & 3;
    const int wm   = wid & 1;      // 2 M-slabs of 64
    const int wn   = wid >> 1;     // 2 N-slabs of 64

    const __half* Az = A + (size_t)blockIdx.z * zA;
    const __half* Bz = B + (size_t)blockIdx.z * zB;
    const int m0 = blockIdx.y * 128;
    const int n0 = blockIdx.x * 128;
    const int NIT = Ktot >> 5;

    // A ldmatrix (x4: 16x16 per mf): lanes 0-15 rows, 16-31 select k-chunk
    const int rowA  = wm * 64 + (lane & 7) + ((lane >> 3) & 1) * 8;  // + mf*16
    const int chA   = (lane >> 4) & 1;                               // + ks*2
    const int swzA  = (rowA >> 1) & 3;
    const uint32_t aoff = (uint32_t)rowA * 64u;
    // B ldmatrix (x4 pairing two nf): lanes 0-7 -> nf-even/ch0, 8-15 -> nf-even/ch1,
    // 16-23 -> nf-odd/ch0, 24-31 -> nf-odd/ch1
    const int rowB  = wn * 64 + (lane & 7) + ((lane >> 4) & 1) * 8;  // + nfp*16
    const int chB   = (lane >> 3) & 1;                               // + ks*2
    const int swzB  = (rowB >> 1) & 3;     // invariant under +16*nfp and +8
    const uint32_t boff = (uint32_t)rowB * 64u;

    // cp.async: per tile 512 16B-chunks; thread covers 4 (A) + 4 (B)
    auto issue = [&](int s, int itk) {
        const int k0 = itk << 5;
        const __half* Ait = Az + (size_t)(k0 >> 9) * slabA + (k0 & 511);
        const __half* Bit = Bz + (size_t)(k0 >> 9) * slabB + (k0 & 511);
        const uint32_t abase = sbu + (uint32_t)s * STAGEB;
        const uint32_t bbase = abase + 8192u;
#pragma unroll
        for (int j = 0; j < 4; j++) {
            const int f = tid + 128 * j;
            const int r = f >> 2, c = f & 3;
            const uint32_t off = (uint32_t)(r * 64) +
                                 ((uint32_t)(c ^ ((r >> 1) & 3)) << 4);
            CP_ASYNC16(abase + off, Ait + (size_t)(m0 + r) * lda + c * 8);
            CP_ASYNC16(bbase + off, Bit + (size_t)(n0 + r) * ldb + c * 8);
        }
    };

    float acc[32][4];
#pragma unroll
    for (int i = 0; i < 32; i++)
#pragma unroll
        for (int j = 0; j < 4; j++) acc[i][j] = 0.f;

    issue(0, 0); CP_COMMIT();
    issue(1, 1); CP_COMMIT();
    issue(2, 2); CP_COMMIT();

    int sc = 0, sp = 3;
    for (int it = 0; it < NIT; it++) {
        if (it < NIT - 2) cp_wait<2>();
        else if (it == NIT - 2) cp_wait<1>();
        else cp_wait<0>();
        __syncthreads();
        // stage sp == (it-1)%4: fully read at iter it-1, proven by barrier above
        if (it + 3 < NIT) { issue(sp, it + 3); CP_COMMIT(); }

        const uint32_t As = sbu + (uint32_t)sc * STAGEB;
        const uint32_t Bs = As + 8192u;
#pragma unroll
        for (int ks = 0; ks < 2; ks++) {
            uint32_t bfr[8][2];
            const uint32_t cB = ((uint32_t)((ks * 2 + chB) ^ swzB)) << 4;
#pragma unroll
            for (int nfp = 0; nfp < 4; nfp++)   // pairs: nf = 2*nfp, 2*nfp+1
                LDSM_X4(bfr[2*nfp][0], bfr[2*nfp][1], bfr[2*nfp+1][0], bfr[2*nfp+1][1],
                        Bs + boff + (uint32_t)nfp * 1024u + cB);
            const uint32_t cA = ((uint32_t)((ks * 2 + chA) ^ swzA)) << 4;
#pragma unroll
            for (int mf = 0; mf < 4; mf++) {
                uint32_t a0, a1, a2, a3;
                LDSM_X4(a0, a1, a2, a3, As + aoff + (uint32_t)mf * 1024u + cA);
#pragma unroll
                for (int nf = 0; nf < 8; nf++)
                    MMA_F16(acc[mf * 8 + nf], a0, a1, a2, a3, bfr[nf][0], bfr[nf][1]);
            }
        }
        sc = (sc + 1) & 3;
        sp = (sp + 1) & 3;
    }

    // ---- epilogue ----
    const float* biasz = (EPI == 1) ? (bias + (size_t)blockIdx.z * zBias) : bias;
#pragma unroll
    for (int mf = 0; mf < 4; mf++) {
        const int r0 = m0 + wm * 64 + mf * 16 + g;
#pragma unroll
        for (int nf = 0; nf < 8; nf++) {
            const int col = n0 + wn * 64 + nf * 8 + 2 * tig;
            float* c = acc[mf * 8 + nf];
            float o0, o1, o2, o3;
            if (EPI == 0) {
                o0 = c[0] * alpha; o1 = c[1] * alpha;
                o2 = c[2] * alpha; o3 = c[3] * alpha;
            } else {
                const float b0v = biasz[col], b1v = biasz[col + 1];
                o0 = c[0] + b0v; o1 = c[1] + b1v;
                o2 = c[2] + b0v; o3 = c[3] + b1v;
            }
            if (HALF_OUT) {
                __half* Ch = (__half*)Cv + (size_t)blockIdx.z * zC;
                *(__half2*)(Ch + (size_t)r0 * ldc + col) =
                    make_half2(__float2half_rn(o0), __float2half_rn(o1));
                *(__half2*)(Ch + (size_t)(r0 + 8) * ldc + col) =
                    make_half2(__float2half_rn(o2), __float2half_rn(o3));
            } else {
                float* Cf = (float*)Cv + (size_t)blockIdx.z * zC;
                *(float2*)(Cf + (size_t)r0 * ldc + col)       = make_float2(o0, o1);
                *(float2*)(Cf + (size_t)(r0 + 8) * ldc + col) = make_float2(o2, o3);
            }
        }
    }
}

// ============================================================
// convert x fp32 -> fp16
// ============================================================
__global__ void __launch_bounds__(256) convert_x_kernel(
    const float* __restrict__ in, __half* __restrict__ out)
{
    const int i = blockIdx.x * 256 + threadIdx.x;
    float4 v = ((const float4*)in)[i];
    __half2* o = (__half2*)(out + (size_t)i * 4);
    o[0] = make_half2(__float2half_rn(v.x), __float2half_rn(v.y));
    o[1] = make_half2(__float2half_rn(v.z), __float2half_rn(v.w));
}

// ============================================================
// concat bq,bk,bv into g_QKVb [3][4][512]
// ============================================================
__global__ void __launch_bounds__(256) concat_bias_kernel(
    const float* __restrict__ bq, const float* __restrict__ bk,
    const float* __restrict__ bv)
{
    const int i = blockIdx.x * 256 + threadIdx.x;   // 0..6143
    const int w = i >> 11, r = i & 2047;
    g_QKVb[i] = (w == 0) ? bq[r] : (w == 1) ? bk[r] : bv[r];
}

// ============================================================
// fused 4-weight transpose fp32 -> fp16: g_Wh[w][n] = W^T
// ============================================================
__global__ void __launch_bounds__(256) transpose_w_kernel(
    const float* __restrict__ Wq, const float* __restrict__ Wk,
    const float* __restrict__ Wv, const float* __restrict__ Wo)
{
    __shared__ float t[32][33];
    const int z = blockIdx.z;
    const int w = z >> 2, n = z & 3;
    const float* src = (w == 0) ? Wq : (w == 1) ? Wk : (w == 2) ? Wv : Wo;
    src += (size_t)n * 262144u;
    __half* dst = g_Wh + (size_t)w * 1048576u + (size_t)n * 262144u;
    const int c0 = blockIdx.x * 32, r0 = blockIdx.y * 32;
    const int x = threadIdx.x, y = threadIdx.y;
#pragma unroll
    for (int j = 0; j < 32; j += 8)
        t[y + j][x] = src[(size_t)(r0 + y + j) * 512u + c0 + x];
    __syncthreads();
#pragma unroll
    for (int j = 0; j < 32; j += 8)
        dst[(size_t)(c0 + y + j) * 512u + r0 + x] = __float2half_rn(t[x][y + j]);
}

// ============================================================
// V (fp16, at g_QKVh + 8M) -> VT (fp16) per (n,b): [1024][512] -> [512][1024]
// ============================================================
__global__ void __launch_bounds__(256) transpose_vh_kernel()
{
    __shared__ __half t[32][33];
    const __half* in = g_QKVh + 8u * 1048576u + (size_t)blockIdx.z * 524288u;
    __half* out = g_VTh + (size_t)blockIdx.z * 524288u;
    const int c0 = blockIdx.x * 32, r0 = blockIdx.y * 32;
    const int x = threadIdx.x, y = threadIdx.y;
#pragma unroll
    for (int j = 0; j < 32; j += 8)
        t[y + j][x] = in[(size_t)(r0 + y + j) * 512u + c0 + x];
    __syncthreads();
#pragma unroll
    for (int j = 0; j < 32; j += 8)
        out[(size_t)(c0 + y + j) * 1024u + r0 + x] = t[x][y + j];
}

// ============================================================
// Softmax-combine: reads fp32 g_S, writes fp16 g_Ph
// ============================================================
__global__ void __launch_bounds__(128) softmax_combine_kernel(
    const float* __restrict__ strength, const float* __restrict__ gate)
{
    __shared__ float sm[4];
    const int r   = blockIdx.x;
    const int n   = r >> 11;
    const float* row = g_S + (size_t)r * 1024u;
    __half* orow = g_Ph + (size_t)r * 1024u;
    const int tid = threadIdx.x;

    float xv[8];
#pragma unroll
    for (int j = 0; j < 8; j++) xv[j] = row[tid + 128 * j];

    float m = xv[0];
#pragma unroll
    for (int j = 1; j < 8; j++) m = fmaxf(m, xv[j]);
#pragma unroll
    for (int o = 16; o; o >>= 1) m = fmaxf(m, __shfl_xor_sync(0xffffffffu, m, o));
    if ((tid & 31) == 0) sm[tid >> 5] = m;
    __syncthreads();
    m = fmaxf(fmaxf(sm[0], sm[1]), fmaxf(sm[2], sm[3]));

    float comb[8] = {0,0,0,0,0,0,0,0};
#pragma unroll 1
    for (int h = 0; h < 8; h++) {
        const float gg = gate[n * 8 + h];
        if (gg != 0.0f) {
            float s = strength[n * 64 + h * 9];
            s = fminf(fmaxf(s, 0.01f), 1.0f);
            float e[8];
            float part = 0.f;
#pragma unroll
            for (int j = 0; j < 8; j++) { e[j] = __expf(s * (xv[j] - m)); part += e[j]; }
#pragma unroll
            for (int o = 16; o; o >>= 1) part += __shfl_xor_sync(0xffffffffu, part, o);
            __syncthreads();
            if ((tid & 31) == 0) sm[tid >> 5] = part;
            __syncthreads();
            const float inv = gg / (sm[0] + sm[1] + sm[2] + sm[3]);
#pragma unroll
            for (int j = 0; j < 8; j++) comb[j] = fmaf(e[j], inv, comb[j]);
        }
    }
#pragma unroll
    for (int j = 0; j < 8; j++) orow[tid + 128 * j] = __float2half_rn(comb[j]);
}

// ============================================================
// combine split-K partials: out = MOD*(p0+p1+p2+p3 + sum_n bo[n])
// ============================================================
__global__ void __launch_bounds__(256) combine_out_kernel(
    const float* __restrict__ bo, float* __restrict__ out)
{
    const int i = blockIdx.x * 256 + threadIdx.x;
    const int col = (i & 127) * 4;
    float4 p0 = ((const float4*)g_OP)[i];
    float4 p1 = ((const float4*)(g_OP + 1048576u))[i];
    float4 p2 = ((const float4*)(g_OP + 2097152u))[i];
    float4 p3 = ((const float4*)(g_OP + 3145728u))[i];
    float4 v;
#pragma unroll
    for (int q = 0; q < 4; q++) {
        const float bsum = bo[col + q] + bo[512 + col + q] +
                           bo[1024 + col + q] + bo[1536 + col + q];
        ((float*)&v)[q] = MODV * (((float*)&p0)[q] + ((float*)&p1)[q] +
                                  ((float*)&p2)[q] + ((float*)&p3)[q] + bsum);
    }
    ((float4*)out)[i] = v;
}

// ============================================================
extern "C" void kernel_launch(void* const* d_in, const int* in_sizes, int n_in,
                              void* d_out, int out_size)
{
    __half *Xh, *Wh, *QKVh, *VTh, *Ph, *HSh;
    float *QKVb, *S, *OP;
    cudaGetSymbolAddress((void**)&Xh,   g_Xh);
    cudaGetSymbolAddress((void**)&Wh,   g_Wh);
    cudaGetSymbolAddress((void**)&QKVb, g_QKVb);
    cudaGetSymbolAddress((void**)&QKVh, g_QKVh);
    cudaGetSymbolAddress((void**)&VTh,  g_VTh);
    cudaGetSymbolAddress((void**)&S,    g_S);
    cudaGetSymbolAddress((void**)&Ph,   g_Ph);
    cudaGetSymbolAddress((void**)&HSh,  g_HSh);
    cudaGetSymbolAddress((void**)&OP,   g_OP);

    const float* x        = (const float*)d_in[0];
    const float* Wq       = (const float*)d_in[1];
    const float* bq       = (const float*)d_in[2];
    const float* Wk       = (const float*)d_in[3];
    const float* bk       = (const float*)d_in[4];
    const float* Wv       = (const float*)d_in[5];
    const float* bv       = (const float*)d_in[6];
    const float* Wo       = (const float*)d_in[7];
    const float* bo       = (const float*)d_in[8];
    const float* strength = (const float*)d_in[9];
    const float* gate     = (const float*)d_in[10];
    float* out = (float*)d_out;

    cudaFuncSetAttribute(gemm_h<0,false>, cudaFuncAttributeMaxDynamicSharedMemorySize, GEMM_SMEM_BYTES);
    cudaFuncSetAttribute(gemm_h<0,true>,  cudaFuncAttributeMaxDynamicSharedMemorySize, GEMM_SMEM_BYTES);
    cudaFuncSetAttribute(gemm_h<1,true>,  cudaFuncAttributeMaxDynamicSharedMemorySize, GEMM_SMEM_BYTES);

    __half* WoT = Wh + 3145728u;
    __half* Qh  = QKVh;
    __half* Kh  = QKVh + 4u * 1048576u;

    const dim3 tb(32, 8);
    convert_x_kernel<<<1024, 256>>>(x, Xh);
    concat_bias_kernel<<<24, 256>>>(bq, bk, bv);
    transpose_w_kernel<<<dim3(16, 16, 16), tb>>>(Wq, Wk, Wv, Wo);

    // 1) QKV fused: z = w*4+n over 12; C[z] = X @ Wh[z]^T + QKVb[z]
    gemm_h<1,true><<<dim3(4, 16, 12), 128, GEMM_SMEM_BYTES>>>(
        Xh, 0, 512, 512,   Wh, 262144u, 512, 512,  QKVb, 512u,
        QKVh, 1048576u, 512, 512, 1.0f);

    // 2) scores = Q @ K^T / sqrt(512), z = (n,b), fp32 out
    gemm_h<0,false><<<dim3(8, 8, 8), 128, GEMM_SMEM_BYTES>>>(
        Qh, 524288u, 512, 512,   Kh, 524288u, 512, 512,  nullptr, 0,
        S, 1048576u, 1024, 512, SCALEV);

    // 3) gated multi-temperature softmax combine: fp32 S -> fp16 P
    softmax_combine_kernel<<<8192, 128>>>(strength, gate);

    // 3b) V^T per (n,b)
    transpose_vh_kernel<<<dim3(16, 32, 8), tb>>>();

    // 4) HS = P @ VT^T, z = (n,b): M=1024, N=512, K=1024, fp16 out
    gemm_h<0,true><<<dim3(4, 8, 8), 128, GEMM_SMEM_BYTES>>>(
        Ph, 1048576u, 512, 1024,   VTh, 524288u, 512, 1024,  nullptr, 0,
        HSh, 524288u, 512, 1024, 1.0f);

    // 5) split-K=4 out partials: z = split s, fp32 out
    gemm_h<0,false><<<dim3(4, 16, 4), 128, GEMM_SMEM_BYTES>>>(
        HSh, 1048576u, 0, 512,   WoT, 262144u, 0, 512,  nullptr, 0,
        OP, 1048576u, 512, 512, 1.0f);

    // 6) out = MOD*(sum partials + sum_n bo)
    combine_out_kernel<<<1024, 256>>>(bo, out);
}